// round 5
// baseline (speedup 1.0000x reference)
#include <cuda_runtime.h>
#include <cstdint>
#include <cstdio>

// ---------------- problem constants ----------------
#define NP 100000
#define NS 50000
#define PD 1024
#define SD 512
#define HF 64
#define EPN 3200000
#define ESN 1600000
#define ELN 2000000

// ---------------- device scratch (static; zero-initialized at load) ----------------
__device__ float g_bufP0[(size_t)NP * HF];
__device__ float g_bufP1[(size_t)NP * HF];
__device__ float g_bufS0[(size_t)NS * HF];
__device__ float g_bufS1[(size_t)NS * HF];
__device__ float g_dinvP[NP];
__device__ float g_dinvS[NS];
__device__ int   g_rowP[NP + 1];
__device__ int   g_rowS[NS + 1];
__device__ int   g_curP[NP];   // counts -> cursor; zero at start of each replay
__device__ int   g_curS[NS];
__device__ int   g_srcP[EPN];
__device__ int   g_srcS[ESN];
__device__ float g_Wc[128 * 64 + 64];   // Wcomb [128,64] row-major, then bcomb[64]
__device__ int   g_bsum[256];

// ================= CSR build (both graphs in shared kernels) =================
__global__ void k_countB(const int* __restrict__ eiP, int EP,
                         const int* __restrict__ eiS, int ES,
                         int* __restrict__ cntP, int* __restrict__ cntS) {
    int e = blockIdx.x * blockDim.x + threadIdx.x;
    if (e < EP) {
        atomicAdd(&cntP[eiP[EP + e]], 1);
    } else if (e < EP + ES) {
        int l = e - EP;
        atomicAdd(&cntS[eiS[ES + l]], 1);
    }
}

__global__ void k_scan1B(const int* __restrict__ cntP, const int* __restrict__ cntS,
                         int* __restrict__ rowP, int* __restrict__ rowS,
                         int* __restrict__ blockSums, int nbP) {
    __shared__ int sh[1024];
    int b = blockIdx.x;
    const int* cnt;
    int* rowOut;
    int N, local0;
    if (b < nbP) { cnt = cntP; rowOut = rowP; N = NP; local0 = b * 1024; }
    else         { cnt = cntS; rowOut = rowS; N = NS; local0 = (b - nbP) * 1024; }
    int i = local0 + threadIdx.x;
    int v = (i < N) ? cnt[i] : 0;
    sh[threadIdx.x] = v;
    __syncthreads();
    for (int off = 1; off < 1024; off <<= 1) {
        int t = 0;
        if ((int)threadIdx.x >= off) t = sh[threadIdx.x - off];
        __syncthreads();
        sh[threadIdx.x] += t;
        __syncthreads();
    }
    int incl = sh[threadIdx.x];
    if (i < N) rowOut[i] = incl - v;
    if (threadIdx.x == 1023) blockSums[b] = incl;
}

__global__ void k_scan2B(int* __restrict__ blockSums, int nbP, int nbS) {
    __shared__ int sh[1024];
    int nb = nbP + nbS;
    int t = threadIdx.x;
    int v = (t < nb) ? blockSums[t] : 0;
    sh[t] = v;
    __syncthreads();
    for (int off = 1; off < 1024; off <<= 1) {
        int x = 0;
        if (t >= off) x = sh[t - off];
        __syncthreads();
        sh[t] += x;
        __syncthreads();
    }
    int excl = sh[t] - v;
    int sumP = sh[nbP - 1];
    if (t < nbP) blockSums[t] = excl;
    else if (t < nb) blockSums[t] = excl - sumP;
}

__global__ void k_scan3B(int* __restrict__ rowP, int* __restrict__ rowS,
                         int* __restrict__ curP, int* __restrict__ curS,
                         const int* __restrict__ blockSums, int nbP,
                         int EP, int ES,
                         float* __restrict__ dinvP, float* __restrict__ dinvS) {
    int i = blockIdx.x * blockDim.x + threadIdx.x;
    if (i < NP) {
        int r = rowP[i] + blockSums[i >> 10];
        int deg = curP[i];
        rowP[i] = r;
        curP[i] = r;
        dinvP[i] = rsqrtf((float)(deg + 1));
        if (i == 0) rowP[NP] = EP;
    } else if (i < NP + NS) {
        int l = i - NP;
        int r = rowS[l] + blockSums[(l >> 10) + nbP];
        int deg = curS[l];
        rowS[l] = r;
        curS[l] = r;
        dinvS[l] = rsqrtf((float)(deg + 1));
        if (l == 0) rowS[NS] = ES;
    }
}

__global__ void k_fillB(const int* __restrict__ eiP, int EP,
                        const int* __restrict__ eiS, int ES,
                        int* __restrict__ curP, int* __restrict__ curS,
                        int* __restrict__ srcP, int* __restrict__ srcS) {
    int e = blockIdx.x * blockDim.x + threadIdx.x;
    if (e < EP) {
        int d = eiP[EP + e];
        int p = atomicAdd(&curP[d], 1);
        srcP[p] = eiP[e];
    } else if (e < EP + ES) {
        int l = e - EP;
        int d = eiS[ES + l];
        int p = atomicAdd(&curS[d], 1);
        srcS[p] = eiS[l];
    }
}

__global__ void k_reset(int* __restrict__ curP, int* __restrict__ curS) {
    int i = blockIdx.x * blockDim.x + threadIdx.x;
    if (i < NP) curP[i] = 0;
    if (i < NS) curS[i] = 0;
}

// ======== fp32 GEMM, FFMA2 + cp.async double buffer ========
// Y[M,64] = X[M,K] @ W[K,64], K % 16 == 0.
#define TMG 256
#define TKG 16

__device__ __forceinline__ unsigned smem_u32(const void* p) {
    return (unsigned)__cvta_generic_to_shared(p);
}
__device__ __forceinline__ void cp16(unsigned dst, const void* src, int srcsz) {
    asm volatile("cp.async.ca.shared.global [%0], [%1], 16, %2;\n"
                 :: "r"(dst), "l"(src), "r"(srcsz));
}
__device__ __forceinline__ void cp_commit() {
    asm volatile("cp.async.commit_group;\n" ::: "memory");
}
__device__ __forceinline__ void cp_wait1() {
    asm volatile("cp.async.wait_group 1;\n" ::: "memory");
}
__device__ __forceinline__ void cp_wait0() {
    asm volatile("cp.async.wait_group 0;\n" ::: "memory");
}

__global__ __launch_bounds__(256, 2) void k_gemm(const float* __restrict__ X,
                                                 const float* __restrict__ W,
                                                 float* __restrict__ Y, int M, int K) {
    // Xs: row-major [row][16] floats, 16B chunks XOR-swizzled by (row>>3)&3
    __shared__ float Xs[2][TMG][TKG];   // 2 x 16 KB
    __shared__ float Ws[2][TKG][HF];    // 2 x 4 KB

    int tid = threadIdx.x;
    int tx = tid & 7;            // col group: cols tx*8 .. tx*8+7
    int ty = tid >> 3;           // row group: rows ty*8 .. ty*8+7
    int row0 = blockIdx.x * TMG;
    int c0 = tx * 8;
    int nt = K / TKG;

    // cp.async assignments
    // X: 256 rows x 4 chunks(16B) = 1024 chunks, 4 per thread
    int xr[4], xc[4];
    const float* xsrc[4];
#pragma unroll
    for (int l = 0; l < 4; l++) {
        int idx = tid + l * 256;
        xr[l] = idx >> 2;          // row in tile
        xc[l] = idx & 3;           // chunk in row
        xsrc[l] = X + (size_t)(row0 + xr[l]) * K + xc[l] * 4;
    }
    // W: 16 rows x 16 chunks = 256 chunks, 1 per thread
    int wkk = tid >> 4;
    int wcc = tid & 15;
    const float* wsrc = W + (size_t)wkk * HF + wcc * 4;

    // issue tile 0
    {
#pragma unroll
        for (int l = 0; l < 4; l++) {
            int gr = row0 + xr[l];
            int swc = xc[l] ^ ((xr[l] >> 3) & 3);
            cp16(smem_u32(&Xs[0][xr[l]][swc * 4]), xsrc[l], (gr < M) ? 16 : 0);
        }
        cp16(smem_u32(&Ws[0][wkk][wcc * 4]), wsrc, 16);
        cp_commit();
    }

    unsigned long long pa[4][8];
#pragma unroll
    for (int p = 0; p < 4; p++)
#pragma unroll
        for (int j = 0; j < 8; j++) pa[p][j] = 0ull;

    int mysw = ty & 3;   // swizzle for my 8 rows (all share row>>3 == ty)

    for (int t = 0; t < nt; t++) {
        int cur = t & 1;
        if (t + 1 < nt) {
            int nxt = 1 - cur;
#pragma unroll
            for (int l = 0; l < 4; l++) {
                int gr = row0 + xr[l];
                int swc = xc[l] ^ ((xr[l] >> 3) & 3);
                cp16(smem_u32(&Xs[nxt][xr[l]][swc * 4]),
                     xsrc[l] + (size_t)(t + 1) * TKG, (gr < M) ? 16 : 0);
            }
            cp16(smem_u32(&Ws[nxt][wkk][wcc * 4]), wsrc + (size_t)(t + 1) * TKG * HF, 16);
            cp_commit();
            cp_wait1();
        } else {
            cp_wait0();
        }
        __syncthreads();

#pragma unroll
        for (int k4 = 0; k4 < 4; k4++) {
            // one float4 per row: Xs[cur][ty*8+i][(k4^mysw)*4 ..]
            float4 xk[8];
#pragma unroll
            for (int i = 0; i < 8; i++)
                xk[i] = *(const float4*)&Xs[cur][ty * 8 + i][(k4 ^ mysw) * 4];
#pragma unroll
            for (int j = 0; j < 4; j++) {
                int kk = k4 * 4 + j;
                float4 wa = *(const float4*)&Ws[cur][kk][c0];
                float4 wb = *(const float4*)&Ws[cur][kk][c0 + 4];
                unsigned long long wd[8];
                asm("mov.b64 %0, {%1, %1};" : "=l"(wd[0]) : "f"(wa.x));
                asm("mov.b64 %0, {%1, %1};" : "=l"(wd[1]) : "f"(wa.y));
                asm("mov.b64 %0, {%1, %1};" : "=l"(wd[2]) : "f"(wa.z));
                asm("mov.b64 %0, {%1, %1};" : "=l"(wd[3]) : "f"(wa.w));
                asm("mov.b64 %0, {%1, %1};" : "=l"(wd[4]) : "f"(wb.x));
                asm("mov.b64 %0, {%1, %1};" : "=l"(wd[5]) : "f"(wb.y));
                asm("mov.b64 %0, {%1, %1};" : "=l"(wd[6]) : "f"(wb.z));
                asm("mov.b64 %0, {%1, %1};" : "=l"(wd[7]) : "f"(wb.w));
                unsigned long long xp[4];
#pragma unroll
                for (int p = 0; p < 4; p++) {
                    const float* f0 = (const float*)&xk[2 * p];
                    const float* f1 = (const float*)&xk[2 * p + 1];
                    asm("mov.b64 %0, {%1, %2};" : "=l"(xp[p]) : "f"(f0[j]), "f"(f1[j]));
                }
#pragma unroll
                for (int p = 0; p < 4; p++)
#pragma unroll
                    for (int q = 0; q < 8; q++)
                        asm("fma.rn.f32x2 %0, %1, %2, %0;"
                            : "+l"(pa[p][q]) : "l"(xp[p]), "l"(wd[q]));
            }
        }
        __syncthreads();
    }

    // unpack and store
#pragma unroll
    for (int p = 0; p < 4; p++) {
        float lo[8], hi[8];
#pragma unroll
        for (int j = 0; j < 8; j++)
            asm("mov.b64 {%0, %1}, %2;" : "=f"(lo[j]), "=f"(hi[j]) : "l"(pa[p][j]));
        int gr0 = row0 + ty * 8 + p * 2;
        if (gr0 < M) {
            *(float4*)(Y + (size_t)gr0 * HF + c0)     = make_float4(lo[0], lo[1], lo[2], lo[3]);
            *(float4*)(Y + (size_t)gr0 * HF + c0 + 4) = make_float4(lo[4], lo[5], lo[6], lo[7]);
        }
        if (gr0 + 1 < M) {
            *(float4*)(Y + (size_t)(gr0 + 1) * HF + c0)     = make_float4(hi[0], hi[1], hi[2], hi[3]);
            *(float4*)(Y + (size_t)(gr0 + 1) * HF + c0 + 4) = make_float4(hi[4], hi[5], hi[6], hi[7]);
        }
    }
}

// ---------------- GCN aggregation (CSR, warp per dst node) ----------------
__global__ void k_aggregate(const float* __restrict__ H, float* __restrict__ OUT,
                            const int* __restrict__ row, const int* __restrict__ srcs,
                            const float* __restrict__ dinv, const float* __restrict__ bias,
                            int N) {
    int warp = (blockIdx.x * blockDim.x + threadIdx.x) >> 5;
    int lane = threadIdx.x & 31;
    if (warp >= N) return;
    int dst = warp;
    float di = dinv[dst];
    const float2* Hp = (const float2*)H;
    float2 hs = Hp[(size_t)dst * 32 + lane];
    float2 acc = make_float2(hs.x * di, hs.y * di);
    int s = row[dst], e = row[dst + 1];
    for (int base = s; base < e; base += 32) {
        int myIdx = 0;
        float myDs = 0.f;
        if (base + lane < e) {
            myIdx = srcs[base + lane];
            myDs  = dinv[myIdx];
        }
        int n = min(32, e - base);
        for (int t = 0; t < n; t++) {
            int src  = __shfl_sync(0xffffffffu, myIdx, t);
            float ds = __shfl_sync(0xffffffffu, myDs, t);
            float2 h = Hp[(size_t)src * 32 + lane];
            acc.x += h.x * ds;
            acc.y += h.y * ds;
        }
    }
    float2 b2 = ((const float2*)bias)[lane];
    float2 o = make_float2(acc.x * di + b2.x, acc.y * di + b2.y);
    ((float2*)OUT)[(size_t)dst * 32 + lane] = o;
}

// ---------------- fold Wproj/Wl1 into Wcomb, bcomb ----------------
__global__ void k_prepWc(const float* __restrict__ Wproj, const float* __restrict__ bproj,
                         const float* __restrict__ Wl1, const float* __restrict__ bl1,
                         float* __restrict__ Wc) {
    __shared__ float sWl1[128 * 64];
    for (int i = threadIdx.x; i < 128 * 64; i += blockDim.x) sWl1[i] = Wl1[i];
    __syncthreads();
    for (int o = threadIdx.x; o < 128 * 64; o += blockDim.x) {
        int i = o >> 6, j = o & 63;
        float s = 0.f;
        for (int k = 0; k < 128; k++) s += Wproj[i * 128 + k] * sWl1[k * 64 + j];
        Wc[o] = s;
    }
    for (int j = threadIdx.x; j < 64; j += blockDim.x) {
        float s = bl1[j];
        for (int k = 0; k < 128; k++) s += bproj[k] * sWl1[k * 64 + j];
        Wc[128 * 64 + j] = s;
    }
}

// ---------------- link predictor: out[e] = relu(Ap[ep]+As[es]+bc) . wl2 + bl2 ----------------
__global__ void k_link(const float* __restrict__ Ap, const float* __restrict__ As,
                       const int* __restrict__ ep, const int* __restrict__ es,
                       const float* __restrict__ bc, const float* __restrict__ wl2,
                       const float* __restrict__ bl2, float* __restrict__ out, int EL) {
    int warp = (blockIdx.x * blockDim.x + threadIdx.x) >> 5;
    int lane = threadIdx.x & 31;
    if (warp >= EL) return;
    int p = ep[warp];
    int s = es[warp];
    float2 a = ((const float2*)Ap)[(size_t)p * 32 + lane];
    float2 b = ((const float2*)As)[(size_t)s * 32 + lane];
    float2 c = ((const float2*)bc)[lane];
    float hx = fmaxf(a.x + b.x + c.x, 0.f);
    float hy = fmaxf(a.y + b.y + c.y, 0.f);
    float2 w = ((const float2*)wl2)[lane];
    float part = hx * w.x + hy * w.y;
#pragma unroll
    for (int off = 16; off; off >>= 1) part += __shfl_xor_sync(0xffffffffu, part, off);
    if (lane == 0) out[warp] = part + bl2[0];
}

// ---------------- host orchestration ----------------
static inline int cdiv(int a, int b) { return (a + b - 1) / b; }

extern "C" void kernel_launch(void* const* d_in, const int* in_sizes, int n_in,
                              void* d_out, int out_size) {
    const float* x_p  = (const float*)d_in[0];
    const float* x_s  = (const float*)d_in[1];
    const int*   ei_p = (const int*)d_in[2];
    const int*   ei_s = (const int*)d_in[3];
    const int*   ed_p = (const int*)d_in[4];
    const int*   ed_s = (const int*)d_in[5];
    const float* Wp1 = (const float*)d_in[6];
    const float* bp1 = (const float*)d_in[7];
    const float* Ws1 = (const float*)d_in[8];
    const float* bs1 = (const float*)d_in[9];
    const float* Wp2 = (const float*)d_in[10];
    const float* bp2 = (const float*)d_in[11];
    const float* Ws2 = (const float*)d_in[12];
    const float* bs2 = (const float*)d_in[13];
    const float* Wproj = (const float*)d_in[14];
    const float* bproj = (const float*)d_in[15];
    const float* Wl1 = (const float*)d_in[16];
    const float* bl1 = (const float*)d_in[17];
    const float* Wl2 = (const float*)d_in[18];
    const float* bl2 = (const float*)d_in[19];
    float* out = (float*)d_out;

    float *bufP0, *bufP1, *bufS0, *bufS1, *dinvP, *dinvS, *Wc;
    int *rowP, *rowS, *curP, *curS, *srcP, *srcS, *bsum;
    cudaGetSymbolAddress((void**)&bufP0, g_bufP0);
    cudaGetSymbolAddress((void**)&bufP1, g_bufP1);
    cudaGetSymbolAddress((void**)&bufS0, g_bufS0);
    cudaGetSymbolAddress((void**)&bufS1, g_bufS1);
    cudaGetSymbolAddress((void**)&dinvP, g_dinvP);
    cudaGetSymbolAddress((void**)&dinvS, g_dinvS);
    cudaGetSymbolAddress((void**)&rowP,  g_rowP);
    cudaGetSymbolAddress((void**)&rowS,  g_rowS);
    cudaGetSymbolAddress((void**)&curP,  g_curP);
    cudaGetSymbolAddress((void**)&curS,  g_curS);
    cudaGetSymbolAddress((void**)&srcP,  g_srcP);
    cudaGetSymbolAddress((void**)&srcS,  g_srcS);
    cudaGetSymbolAddress((void**)&Wc,    g_Wc);
    cudaGetSymbolAddress((void**)&bsum,  g_bsum);

    const int EP = in_sizes[2] / 2;
    const int ES = in_sizes[3] / 2;
    const int EL = in_sizes[4];
    const int nbP = cdiv(NP, 1024), nbS = cdiv(NS, 1024);

    // ---- CSR build prefix; big GEMM placed as 4th launch (lands in ncu window) ----
    k_countB<<<cdiv(EP + ES, 256), 256>>>(ei_p, EP, ei_s, ES, curP, curS);
    k_scan1B<<<nbP + nbS, 1024>>>(curP, curS, rowP, rowS, bsum, nbP);
    k_scan2B<<<1, 1024>>>(bsum, nbP, nbS);
    k_gemm<<<cdiv(NP, TMG), 256>>>(x_p, Wp1, bufP0, NP, PD);     // <- profiled launch
    k_scan3B<<<cdiv(NP + NS, 256), 256>>>(rowP, rowS, curP, curS, bsum, nbP, EP, ES, dinvP, dinvS);
    k_fillB<<<cdiv(EP + ES, 256), 256>>>(ei_p, EP, ei_s, ES, curP, curS, srcP, srcS);
    k_gemm<<<cdiv(NS, TMG), 256>>>(x_s, Ws1, bufS0, NS, SD);
    k_prepWc<<<1, 256>>>(Wproj, bproj, Wl1, bl1, Wc);

    // ---- protein GCN ----
    k_aggregate<<<cdiv(NP * 32, 256), 256>>>(bufP0, bufP1, rowP, srcP, dinvP, bp1, NP);
    k_gemm<<<cdiv(NP, TMG), 256>>>(bufP1, Wp2, bufP0, NP, HF);
    k_aggregate<<<cdiv(NP * 32, 256), 256>>>(bufP0, bufP1, rowP, srcP, dinvP, bp2, NP);

    // ---- substrate GCN ----
    k_aggregate<<<cdiv(NS * 32, 256), 256>>>(bufS0, bufS1, rowS, srcS, dinvS, bs1, NS);
    k_gemm<<<cdiv(NS, TMG), 256>>>(bufS1, Ws2, bufS0, NS, HF);
    k_aggregate<<<cdiv(NS * 32, 256), 256>>>(bufS0, bufS1, rowS, srcS, dinvS, bs2, NS);

    // ---- per-node link features: Ap = z_p @ Wc_top, As = z_s @ Wc_bot ----
    k_gemm<<<cdiv(NP, TMG), 256>>>(bufP1, Wc, bufP0, NP, HF);
    k_gemm<<<cdiv(NS, TMG), 256>>>(bufS1, Wc + 64 * 64, bufS0, NS, HF);

    // ---- link prediction ----
    {
        long long threads = (long long)EL * 32;
        int blocks = (int)((threads + 255) / 256);
        k_link<<<blocks, 256>>>(bufP0, bufS0, ed_p, ed_s, Wc + 128 * 64, Wl2, bl2, out, EL);
    }

    // ---- restore cursor arrays for next replay ----
    k_reset<<<cdiv(NP, 256), 256>>>(curP, curS);
}

// round 6
// speedup vs baseline: 2.0895x; 2.0895x over previous
#include <cuda_runtime.h>
#include <cstdint>
#include <cstdio>

// ---------------- problem constants ----------------
#define NP 100000
#define NS 50000
#define PD 1024
#define SD 512
#define HF 64
#define EPN 3200000
#define ESN 1600000
#define ELN 2000000

// ---------------- device scratch (static; zero-initialized at load) ----------------
__device__ float g_bufP0[(size_t)NP * HF];
__device__ float g_bufP1[(size_t)NP * HF];
__device__ float g_bufS0[(size_t)NS * HF];
__device__ float g_bufS1[(size_t)NS * HF];
__device__ float g_dinvP[NP];
__device__ float g_dinvS[NS];
__device__ int   g_rowP[NP + 1];
__device__ int   g_rowS[NS + 1];
__device__ int   g_curP[NP];   // counts -> cursor; zero at start of each replay
__device__ int   g_curS[NS];
__device__ int   g_srcP[EPN];
__device__ int   g_srcS[ESN];
__device__ float g_Wc[128 * 64 + 64];   // Wcomb [128,64] row-major, then bcomb[64]
__device__ int   g_bsum[256];

// ================= CSR build (both graphs in shared kernels) =================
__global__ void k_countB(const int* __restrict__ eiP, int EP,
                         const int* __restrict__ eiS, int ES,
                         int* __restrict__ cntP, int* __restrict__ cntS) {
    int e = blockIdx.x * blockDim.x + threadIdx.x;
    if (e < EP) {
        atomicAdd(&cntP[eiP[EP + e]], 1);
    } else if (e < EP + ES) {
        int l = e - EP;
        atomicAdd(&cntS[eiS[ES + l]], 1);
    }
}

__global__ void k_scan1B(const int* __restrict__ cntP, const int* __restrict__ cntS,
                         int* __restrict__ rowP, int* __restrict__ rowS,
                         int* __restrict__ blockSums, int nbP) {
    __shared__ int sh[1024];
    int b = blockIdx.x;
    const int* cnt;
    int* rowOut;
    int N, local0;
    if (b < nbP) { cnt = cntP; rowOut = rowP; N = NP; local0 = b * 1024; }
    else         { cnt = cntS; rowOut = rowS; N = NS; local0 = (b - nbP) * 1024; }
    int i = local0 + threadIdx.x;
    int v = (i < N) ? cnt[i] : 0;
    sh[threadIdx.x] = v;
    __syncthreads();
    for (int off = 1; off < 1024; off <<= 1) {
        int t = 0;
        if ((int)threadIdx.x >= off) t = sh[threadIdx.x - off];
        __syncthreads();
        sh[threadIdx.x] += t;
        __syncthreads();
    }
    int incl = sh[threadIdx.x];
    if (i < N) rowOut[i] = incl - v;
    if (threadIdx.x == 1023) blockSums[b] = incl;
}

__global__ void k_scan2B(int* __restrict__ blockSums, int nbP, int nbS) {
    __shared__ int sh[1024];
    int nb = nbP + nbS;
    int t = threadIdx.x;
    int v = (t < nb) ? blockSums[t] : 0;
    sh[t] = v;
    __syncthreads();
    for (int off = 1; off < 1024; off <<= 1) {
        int x = 0;
        if (t >= off) x = sh[t - off];
        __syncthreads();
        sh[t] += x;
        __syncthreads();
    }
    int excl = sh[t] - v;
    int sumP = sh[nbP - 1];
    if (t < nbP) blockSums[t] = excl;
    else if (t < nb) blockSums[t] = excl - sumP;
}

__global__ void k_scan3B(int* __restrict__ rowP, int* __restrict__ rowS,
                         int* __restrict__ curP, int* __restrict__ curS,
                         const int* __restrict__ blockSums, int nbP,
                         int EP, int ES,
                         float* __restrict__ dinvP, float* __restrict__ dinvS) {
    int i = blockIdx.x * blockDim.x + threadIdx.x;
    if (i < NP) {
        int r = rowP[i] + blockSums[i >> 10];
        int deg = curP[i];
        rowP[i] = r;
        curP[i] = r;
        dinvP[i] = rsqrtf((float)(deg + 1));
        if (i == 0) rowP[NP] = EP;
    } else if (i < NP + NS) {
        int l = i - NP;
        int r = rowS[l] + blockSums[(l >> 10) + nbP];
        int deg = curS[l];
        rowS[l] = r;
        curS[l] = r;
        dinvS[l] = rsqrtf((float)(deg + 1));
        if (l == 0) rowS[NS] = ES;
    }
}

__global__ void k_fillB(const int* __restrict__ eiP, int EP,
                        const int* __restrict__ eiS, int ES,
                        int* __restrict__ curP, int* __restrict__ curS,
                        int* __restrict__ srcP, int* __restrict__ srcS) {
    int e = blockIdx.x * blockDim.x + threadIdx.x;
    if (e < EP) {
        int d = eiP[EP + e];
        int p = atomicAdd(&curP[d], 1);
        srcP[p] = eiP[e];
    } else if (e < EP + ES) {
        int l = e - EP;
        int d = eiS[ES + l];
        int p = atomicAdd(&curS[d], 1);
        srcS[p] = eiS[l];
    }
}

__global__ void k_reset(int* __restrict__ curP, int* __restrict__ curS) {
    int i = blockIdx.x * blockDim.x + threadIdx.x;
    if (i < NP) curP[i] = 0;
    if (i < NS) curS[i] = 0;
}

// ======== tf32 tensor-core GEMM: Y[M,64] = X[M,K] @ W[K,64], K % 32 == 0 ========
// Block: 128 rows x 64 cols, BK=32. 8 warps: warp (w%4) -> rows (w%4)*32,
// (w/4) -> cols (w/4)*32. Warp computes 32x32 via 2x4 grid of m16n8k8 MMAs.
#define BM 128
#define BN 64
#define BK 32
#define XPAD 40   // floats per Xs row: A-frag bank = 8*(lane/4)+lane%4, conflict-free
#define WPAD 72   // floats per Ws row: B-frag bank = 8*(lane%4)+lane/4, conflict-free

__device__ __forceinline__ unsigned f2tf32(float f) {
    unsigned u;
    asm("cvt.rna.tf32.f32 %0, %1;" : "=r"(u) : "f"(f));
    return u;
}

__global__ __launch_bounds__(256, 2) void k_gemm(const float* __restrict__ X,
                                                 const float* __restrict__ W,
                                                 float* __restrict__ Y, int M, int K) {
    __shared__ unsigned Xs[BM * XPAD];   // 20 KB
    __shared__ unsigned Ws[BK * WPAD];   // 9 KB

    int tid = threadIdx.x;
    int wid = tid >> 5, lane = tid & 31;
    int lq = lane >> 2;      // 0..7 (group)
    int lr = lane & 3;       // 0..3 (thread-in-group)
    int rb = (wid & 3) * 32; // warp row base in tile
    int cb = (wid >> 2) * 32;// warp col base
    int row0 = blockIdx.x * BM;
    int nt = K / BK;

    // LDG assignment: X tile 128r x 8 float4-chunks = 1024, 4/thread
    int xr[4], xc[4];
#pragma unroll
    for (int l = 0; l < 4; l++) {
        int idx = tid + l * 256;
        xr[l] = idx >> 3;
        xc[l] = idx & 7;
    }
    // W tile: 32k x 16 float4-chunks = 512, 2/thread
    int wk[2], wc[2];
#pragma unroll
    for (int l = 0; l < 2; l++) {
        int idx = tid + l * 256;
        wk[l] = idx >> 4;
        wc[l] = idx & 15;
    }

    float acc[2][4][4];
#pragma unroll
    for (int mt = 0; mt < 2; mt++)
#pragma unroll
        for (int nb = 0; nb < 4; nb++)
#pragma unroll
            for (int j = 0; j < 4; j++) acc[mt][nb][j] = 0.f;

    float4 xv[4], wv[2];
    // prologue: LDG tile 0
#pragma unroll
    for (int l = 0; l < 4; l++) {
        int gr = row0 + xr[l];
        xv[l] = (gr < M) ? *(const float4*)(X + (size_t)gr * K + xc[l] * 4)
                         : make_float4(0.f, 0.f, 0.f, 0.f);
    }
#pragma unroll
    for (int l = 0; l < 2; l++)
        wv[l] = *(const float4*)(W + (size_t)wk[l] * HF + wc[l] * 4);
    // STS tile 0
#pragma unroll
    for (int l = 0; l < 4; l++) {
        uint4 u = make_uint4(f2tf32(xv[l].x), f2tf32(xv[l].y), f2tf32(xv[l].z), f2tf32(xv[l].w));
        *(uint4*)&Xs[xr[l] * XPAD + xc[l] * 4] = u;
    }
#pragma unroll
    for (int l = 0; l < 2; l++) {
        uint4 u = make_uint4(f2tf32(wv[l].x), f2tf32(wv[l].y), f2tf32(wv[l].z), f2tf32(wv[l].w));
        *(uint4*)&Ws[wk[l] * WPAD + wc[l] * 4] = u;
    }
    __syncthreads();

    for (int t = 0; t < nt; t++) {
        // prefetch next tile into registers
        if (t + 1 < nt) {
            const float* Xn = X + (size_t)(t + 1) * BK;
            const float* Wn = W + (size_t)(t + 1) * BK * HF;
#pragma unroll
            for (int l = 0; l < 4; l++) {
                int gr = row0 + xr[l];
                xv[l] = (gr < M) ? *(const float4*)(Xn + (size_t)gr * K + xc[l] * 4)
                                 : make_float4(0.f, 0.f, 0.f, 0.f);
            }
#pragma unroll
            for (int l = 0; l < 2; l++)
                wv[l] = *(const float4*)(Wn + (size_t)wk[l] * HF + wc[l] * 4);
        }

        // compute on smem tile
#pragma unroll
        for (int ks = 0; ks < 4; ks++) {
            int k0 = ks * 8;
            unsigned a[2][4];
#pragma unroll
            for (int mt = 0; mt < 2; mt++) {
                int r = rb + mt * 16 + lq;
                a[mt][0] = Xs[r * XPAD + k0 + lr];
                a[mt][1] = Xs[(r + 8) * XPAD + k0 + lr];
                a[mt][2] = Xs[r * XPAD + k0 + 4 + lr];
                a[mt][3] = Xs[(r + 8) * XPAD + k0 + 4 + lr];
            }
            unsigned b[4][2];
#pragma unroll
            for (int nb = 0; nb < 4; nb++) {
                int c = cb + nb * 8 + lq;
                b[nb][0] = Ws[(k0 + lr) * WPAD + c];
                b[nb][1] = Ws[(k0 + 4 + lr) * WPAD + c];
            }
#pragma unroll
            for (int mt = 0; mt < 2; mt++)
#pragma unroll
                for (int nb = 0; nb < 4; nb++)
                    asm volatile(
                        "mma.sync.aligned.m16n8k8.row.col.f32.tf32.tf32.f32 "
                        "{%0,%1,%2,%3}, {%4,%5,%6,%7}, {%8,%9}, {%0,%1,%2,%3};"
                        : "+f"(acc[mt][nb][0]), "+f"(acc[mt][nb][1]),
                          "+f"(acc[mt][nb][2]), "+f"(acc[mt][nb][3])
                        : "r"(a[mt][0]), "r"(a[mt][1]), "r"(a[mt][2]), "r"(a[mt][3]),
                          "r"(b[nb][0]), "r"(b[nb][1]));
        }
        __syncthreads();

        if (t + 1 < nt) {
#pragma unroll
            for (int l = 0; l < 4; l++) {
                uint4 u = make_uint4(f2tf32(xv[l].x), f2tf32(xv[l].y), f2tf32(xv[l].z), f2tf32(xv[l].w));
                *(uint4*)&Xs[xr[l] * XPAD + xc[l] * 4] = u;
            }
#pragma unroll
            for (int l = 0; l < 2; l++) {
                uint4 u = make_uint4(f2tf32(wv[l].x), f2tf32(wv[l].y), f2tf32(wv[l].z), f2tf32(wv[l].w));
                *(uint4*)&Ws[wk[l] * WPAD + wc[l] * 4] = u;
            }
            __syncthreads();
        }
    }

    // epilogue: C frag: c0,c1 -> row lq, cols 2*lr+{0,1}; c2,c3 -> row lq+8
#pragma unroll
    for (int mt = 0; mt < 2; mt++) {
#pragma unroll
        for (int nb = 0; nb < 4; nb++) {
            int r = row0 + rb + mt * 16 + lq;
            int c = cb + nb * 8 + 2 * lr;
            if (r < M)
                *(float2*)(Y + (size_t)r * HF + c) = make_float2(acc[mt][nb][0], acc[mt][nb][1]);
            if (r + 8 < M)
                *(float2*)(Y + (size_t)(r + 8) * HF + c) = make_float2(acc[mt][nb][2], acc[mt][nb][3]);
        }
    }
}

// ---------------- GCN aggregation (CSR, warp per dst node) ----------------
__global__ void k_aggregate(const float* __restrict__ H, float* __restrict__ OUT,
                            const int* __restrict__ row, const int* __restrict__ srcs,
                            const float* __restrict__ dinv, const float* __restrict__ bias,
                            int N) {
    int warp = (blockIdx.x * blockDim.x + threadIdx.x) >> 5;
    int lane = threadIdx.x & 31;
    if (warp >= N) return;
    int dst = warp;
    float di = dinv[dst];
    const float2* Hp = (const float2*)H;
    float2 hs = Hp[(size_t)dst * 32 + lane];
    float2 acc = make_float2(hs.x * di, hs.y * di);
    int s = row[dst], e = row[dst + 1];
    for (int base = s; base < e; base += 32) {
        int myIdx = 0;
        float myDs = 0.f;
        if (base + lane < e) {
            myIdx = srcs[base + lane];
            myDs  = dinv[myIdx];
        }
        int n = min(32, e - base);
        for (int t = 0; t < n; t++) {
            int src  = __shfl_sync(0xffffffffu, myIdx, t);
            float ds = __shfl_sync(0xffffffffu, myDs, t);
            float2 h = Hp[(size_t)src * 32 + lane];
            acc.x += h.x * ds;
            acc.y += h.y * ds;
        }
    }
    float2 b2 = ((const float2*)bias)[lane];
    float2 o = make_float2(acc.x * di + b2.x, acc.y * di + b2.y);
    ((float2*)OUT)[(size_t)dst * 32 + lane] = o;
}

// ---------------- fold Wproj/Wl1 into Wcomb, bcomb ----------------
__global__ void k_prepWc(const float* __restrict__ Wproj, const float* __restrict__ bproj,
                         const float* __restrict__ Wl1, const float* __restrict__ bl1,
                         float* __restrict__ Wc) {
    __shared__ float sWl1[128 * 64];
    for (int i = threadIdx.x; i < 128 * 64; i += blockDim.x) sWl1[i] = Wl1[i];
    __syncthreads();
    for (int o = threadIdx.x; o < 128 * 64; o += blockDim.x) {
        int i = o >> 6, j = o & 63;
        float s = 0.f;
        for (int k = 0; k < 128; k++) s += Wproj[i * 128 + k] * sWl1[k * 64 + j];
        Wc[o] = s;
    }
    for (int j = threadIdx.x; j < 64; j += blockDim.x) {
        float s = bl1[j];
        for (int k = 0; k < 128; k++) s += bproj[k] * sWl1[k * 64 + j];
        Wc[128 * 64 + j] = s;
    }
}

// ---------------- link predictor: out[e] = relu(Ap[ep]+As[es]+bc) . wl2 + bl2 ----------------
__global__ void k_link(const float* __restrict__ Ap, const float* __restrict__ As,
                       const int* __restrict__ ep, const int* __restrict__ es,
                       const float* __restrict__ bc, const float* __restrict__ wl2,
                       const float* __restrict__ bl2, float* __restrict__ out, int EL) {
    int warp = (blockIdx.x * blockDim.x + threadIdx.x) >> 5;
    int lane = threadIdx.x & 31;
    if (warp >= EL) return;
    int p = ep[warp];
    int s = es[warp];
    float2 a = ((const float2*)Ap)[(size_t)p * 32 + lane];
    float2 b = ((const float2*)As)[(size_t)s * 32 + lane];
    float2 c = ((const float2*)bc)[lane];
    float hx = fmaxf(a.x + b.x + c.x, 0.f);
    float hy = fmaxf(a.y + b.y + c.y, 0.f);
    float2 w = ((const float2*)wl2)[lane];
    float part = hx * w.x + hy * w.y;
#pragma unroll
    for (int off = 16; off; off >>= 1) part += __shfl_xor_sync(0xffffffffu, part, off);
    if (lane == 0) out[warp] = part + bl2[0];
}

// ---------------- host orchestration ----------------
static inline int cdiv(int a, int b) { return (a + b - 1) / b; }

extern "C" void kernel_launch(void* const* d_in, const int* in_sizes, int n_in,
                              void* d_out, int out_size) {
    const float* x_p  = (const float*)d_in[0];
    const float* x_s  = (const float*)d_in[1];
    const int*   ei_p = (const int*)d_in[2];
    const int*   ei_s = (const int*)d_in[3];
    const int*   ed_p = (const int*)d_in[4];
    const int*   ed_s = (const int*)d_in[5];
    const float* Wp1 = (const float*)d_in[6];
    const float* bp1 = (const float*)d_in[7];
    const float* Ws1 = (const float*)d_in[8];
    const float* bs1 = (const float*)d_in[9];
    const float* Wp2 = (const float*)d_in[10];
    const float* bp2 = (const float*)d_in[11];
    const float* Ws2 = (const float*)d_in[12];
    const float* bs2 = (const float*)d_in[13];
    const float* Wproj = (const float*)d_in[14];
    const float* bproj = (const float*)d_in[15];
    const float* Wl1 = (const float*)d_in[16];
    const float* bl1 = (const float*)d_in[17];
    const float* Wl2 = (const float*)d_in[18];
    const float* bl2 = (const float*)d_in[19];
    float* out = (float*)d_out;

    float *bufP0, *bufP1, *bufS0, *bufS1, *dinvP, *dinvS, *Wc;
    int *rowP, *rowS, *curP, *curS, *srcP, *srcS, *bsum;
    cudaGetSymbolAddress((void**)&bufP0, g_bufP0);
    cudaGetSymbolAddress((void**)&bufP1, g_bufP1);
    cudaGetSymbolAddress((void**)&bufS0, g_bufS0);
    cudaGetSymbolAddress((void**)&bufS1, g_bufS1);
    cudaGetSymbolAddress((void**)&dinvP, g_dinvP);
    cudaGetSymbolAddress((void**)&dinvS, g_dinvS);
    cudaGetSymbolAddress((void**)&rowP,  g_rowP);
    cudaGetSymbolAddress((void**)&rowS,  g_rowS);
    cudaGetSymbolAddress((void**)&curP,  g_curP);
    cudaGetSymbolAddress((void**)&curS,  g_curS);
    cudaGetSymbolAddress((void**)&srcP,  g_srcP);
    cudaGetSymbolAddress((void**)&srcS,  g_srcS);
    cudaGetSymbolAddress((void**)&Wc,    g_Wc);
    cudaGetSymbolAddress((void**)&bsum,  g_bsum);

    const int EP = in_sizes[2] / 2;
    const int ES = in_sizes[3] / 2;
    const int EL = in_sizes[4];
    const int nbP = cdiv(NP, 1024), nbS = cdiv(NS, 1024);

    // ---- CSR build prefix; big GEMM placed as 4th launch (lands in ncu window) ----
    k_countB<<<cdiv(EP + ES, 256), 256>>>(ei_p, EP, ei_s, ES, curP, curS);
    k_scan1B<<<nbP + nbS, 1024>>>(curP, curS, rowP, rowS, bsum, nbP);
    k_scan2B<<<1, 1024>>>(bsum, nbP, nbS);
    k_gemm<<<cdiv(NP, BM), 256>>>(x_p, Wp1, bufP0, NP, PD);     // <- profiled launch
    k_scan3B<<<cdiv(NP + NS, 256), 256>>>(rowP, rowS, curP, curS, bsum, nbP, EP, ES, dinvP, dinvS);
    k_fillB<<<cdiv(EP + ES, 256), 256>>>(ei_p, EP, ei_s, ES, curP, curS, srcP, srcS);
    k_gemm<<<cdiv(NS, BM), 256>>>(x_s, Ws1, bufS0, NS, SD);
    k_prepWc<<<1, 256>>>(Wproj, bproj, Wl1, bl1, Wc);

    // ---- protein GCN ----
    k_aggregate<<<cdiv(NP * 32, 256), 256>>>(bufP0, bufP1, rowP, srcP, dinvP, bp1, NP);
    k_gemm<<<cdiv(NP, BM), 256>>>(bufP1, Wp2, bufP0, NP, HF);
    k_aggregate<<<cdiv(NP * 32, 256), 256>>>(bufP0, bufP1, rowP, srcP, dinvP, bp2, NP);

    // ---- substrate GCN ----
    k_aggregate<<<cdiv(NS * 32, 256), 256>>>(bufS0, bufS1, rowS, srcS, dinvS, bs1, NS);
    k_gemm<<<cdiv(NS, BM), 256>>>(bufS1, Ws2, bufS0, NS, HF);
    k_aggregate<<<cdiv(NS * 32, 256), 256>>>(bufS0, bufS1, rowS, srcS, dinvS, bs2, NS);

    // ---- per-node link features: Ap = z_p @ Wc_top, As = z_s @ Wc_bot ----
    k_gemm<<<cdiv(NP, BM), 256>>>(bufP1, Wc, bufP0, NP, HF);
    k_gemm<<<cdiv(NS, BM), 256>>>(bufS1, Wc + 64 * 64, bufS0, NS, HF);

    // ---- link prediction ----
    {
        long long threads = (long long)EL * 32;
        int blocks = (int)((threads + 255) / 256);
        k_link<<<blocks, 256>>>(bufP0, bufS0, ed_p, ed_s, Wc + 128 * 64, Wl2, bl2, out, EL);
    }

    // ---- restore cursor arrays for next replay ----
    k_reset<<<cdiv(NP, 256), 256>>>(curP, curS);
}

// round 7
// speedup vs baseline: 2.2739x; 1.0883x over previous
#include <cuda_runtime.h>
#include <cstdint>
#include <cstdio>

// ---------------- problem constants ----------------
#define NP 100000
#define NS 50000
#define PD 1024
#define SD 512
#define HF 64
#define EPN 3200000
#define ESN 1600000
#define ELN 2000000

// ---------------- device scratch (static; zero-initialized at load) ----------------
__device__ float g_bufP0[(size_t)NP * HF];
__device__ float g_bufP1[(size_t)NP * HF];
__device__ float g_bufS0[(size_t)NS * HF];
__device__ float g_bufS1[(size_t)NS * HF];
__device__ float g_dinvP[NP];
__device__ float g_dinvS[NS];
__device__ int   g_rowP[NP + 1];
__device__ int   g_rowS[NS + 1];
__device__ int   g_curP[NP];   // counts -> cursor; zero at start of each replay
__device__ int   g_curS[NS];
__device__ int   g_srcP[EPN];
__device__ int   g_srcS[ESN];
__device__ float g_Wc[128 * 64 + 64];   // Wcomb [128,64] row-major, then bcomb[64]
__device__ int   g_bsum[256];

// ================= CSR build (both graphs in shared kernels) =================
__global__ void k_countB(const int* __restrict__ eiP, int EP,
                         const int* __restrict__ eiS, int ES,
                         int* __restrict__ cntP, int* __restrict__ cntS) {
    int e = blockIdx.x * blockDim.x + threadIdx.x;
    if (e < EP) {
        atomicAdd(&cntP[eiP[EP + e]], 1);
    } else if (e < EP + ES) {
        int l = e - EP;
        atomicAdd(&cntS[eiS[ES + l]], 1);
    }
}

__global__ void k_scan1B(const int* __restrict__ cntP, const int* __restrict__ cntS,
                         int* __restrict__ rowP, int* __restrict__ rowS,
                         int* __restrict__ blockSums, int nbP) {
    __shared__ int sh[1024];
    int b = blockIdx.x;
    const int* cnt;
    int* rowOut;
    int N, local0;
    if (b < nbP) { cnt = cntP; rowOut = rowP; N = NP; local0 = b * 1024; }
    else         { cnt = cntS; rowOut = rowS; N = NS; local0 = (b - nbP) * 1024; }
    int i = local0 + threadIdx.x;
    int v = (i < N) ? cnt[i] : 0;
    sh[threadIdx.x] = v;
    __syncthreads();
    for (int off = 1; off < 1024; off <<= 1) {
        int t = 0;
        if ((int)threadIdx.x >= off) t = sh[threadIdx.x - off];
        __syncthreads();
        sh[threadIdx.x] += t;
        __syncthreads();
    }
    int incl = sh[threadIdx.x];
    if (i < N) rowOut[i] = incl - v;
    if (threadIdx.x == 1023) blockSums[b] = incl;
}

__global__ void k_scan2B(int* __restrict__ blockSums, int nbP, int nbS) {
    __shared__ int sh[1024];
    int nb = nbP + nbS;
    int t = threadIdx.x;
    int v = (t < nb) ? blockSums[t] : 0;
    sh[t] = v;
    __syncthreads();
    for (int off = 1; off < 1024; off <<= 1) {
        int x = 0;
        if (t >= off) x = sh[t - off];
        __syncthreads();
        sh[t] += x;
        __syncthreads();
    }
    int excl = sh[t] - v;
    int sumP = sh[nbP - 1];
    if (t < nbP) blockSums[t] = excl;
    else if (t < nb) blockSums[t] = excl - sumP;
}

__global__ void k_scan3B(int* __restrict__ rowP, int* __restrict__ rowS,
                         int* __restrict__ curP, int* __restrict__ curS,
                         const int* __restrict__ blockSums, int nbP,
                         int EP, int ES,
                         float* __restrict__ dinvP, float* __restrict__ dinvS) {
    int i = blockIdx.x * blockDim.x + threadIdx.x;
    if (i < NP) {
        int r = rowP[i] + blockSums[i >> 10];
        int deg = curP[i];
        rowP[i] = r;
        curP[i] = r;
        dinvP[i] = rsqrtf((float)(deg + 1));
        if (i == 0) rowP[NP] = EP;
    } else if (i < NP + NS) {
        int l = i - NP;
        int r = rowS[l] + blockSums[(l >> 10) + nbP];
        int deg = curS[l];
        rowS[l] = r;
        curS[l] = r;
        dinvS[l] = rsqrtf((float)(deg + 1));
        if (l == 0) rowS[NS] = ES;
    }
}

__global__ void k_fillB(const int* __restrict__ eiP, int EP,
                        const int* __restrict__ eiS, int ES,
                        int* __restrict__ curP, int* __restrict__ curS,
                        int* __restrict__ srcP, int* __restrict__ srcS) {
    int e = blockIdx.x * blockDim.x + threadIdx.x;
    if (e < EP) {
        int d = eiP[EP + e];
        int p = atomicAdd(&curP[d], 1);
        srcP[p] = eiP[e];
    } else if (e < EP + ES) {
        int l = e - EP;
        int d = eiS[ES + l];
        int p = atomicAdd(&curS[d], 1);
        srcS[p] = eiS[l];
    }
}

__global__ void k_reset(int* __restrict__ curP, int* __restrict__ curS) {
    int i = blockIdx.x * blockDim.x + threadIdx.x;
    if (i < NP) curP[i] = 0;
    if (i < NS) curS[i] = 0;
}

// ======== tf32 tensor-core GEMM, 4 warps, 2x2 warp grid, cp.async X path ========
// Y[M,64] = X[M,K] @ W[K,64], K % 32 == 0.
// Block: 128 rows x 64 cols, BK=32, 128 threads. Warp (w&1) -> rows (w&1)*64,
// (w>>1) -> cols (w>>1)*32. Warp computes 64x32 via 4x4 grid of m16n8k8 MMAs.
#define BM 128
#define BN 64
#define BK 32
#define XPAD 36   // fp32/row; A-frag bank = (4*lq+lr) mod 32 -> conflict-free
#define WPAD 72   // tf32/row; B-frag bank = (8*lr+lq) mod 32 -> conflict-free
#define XSTAGE (BM * XPAD)           // floats per X stage (18432 B)
#define WSTAGE (BK * WPAD)           // words per W stage (9216 B)
#define GEMM_SMEM (2 * XSTAGE * 4 + 2 * WSTAGE * 4)   // 55296 B

__device__ __forceinline__ unsigned f2tf32(float f) {
    unsigned u;
    asm("cvt.rna.tf32.f32 %0, %1;" : "=r"(u) : "f"(f));
    return u;
}
__device__ __forceinline__ unsigned smem_u32g(const void* p) {
    return (unsigned)__cvta_generic_to_shared(p);
}
__device__ __forceinline__ void cp16g(unsigned dst, const void* src, int srcsz) {
    asm volatile("cp.async.ca.shared.global [%0], [%1], 16, %2;\n"
                 :: "r"(dst), "l"(src), "r"(srcsz));
}
__device__ __forceinline__ void cp_commitg() {
    asm volatile("cp.async.commit_group;\n" ::: "memory");
}
__device__ __forceinline__ void cp_waitg1() {
    asm volatile("cp.async.wait_group 1;\n" ::: "memory");
}
__device__ __forceinline__ void cp_waitg0() {
    asm volatile("cp.async.wait_group 0;\n" ::: "memory");
}

__global__ __launch_bounds__(128, 3) void k_gemm(const float* __restrict__ X,
                                                 const float* __restrict__ W,
                                                 float* __restrict__ Y, int M, int K) {
    extern __shared__ char dynsmem[];
    float*    Xs = (float*)dynsmem;                     // [2][BM*XPAD]
    unsigned* Ws = (unsigned*)(dynsmem + 2 * XSTAGE * 4); // [2][BK*WPAD]

    int tid = threadIdx.x;
    int wid = tid >> 5, lane = tid & 31;
    int lq = lane >> 2;       // 0..7
    int lr = lane & 3;        // 0..3
    int rb = (wid & 1) * 64;  // warp row base
    int cb = (wid >> 1) * 32; // warp col base
    int row0 = blockIdx.x * BM;
    int nt = K / BK;

    // X cp.async: 128 rows x 8 chunks(16B) = 1024, 8 per thread
    int xr[8], xc[8];
#pragma unroll
    for (int l = 0; l < 8; l++) {
        int idx = tid + l * 128;
        xr[l] = idx >> 3;
        xc[l] = idx & 7;
    }
    // W register path: 32k x 16 chunks = 512, 4 per thread
    int wk[4], wc[4];
#pragma unroll
    for (int l = 0; l < 4; l++) {
        int idx = tid + l * 128;
        wk[l] = idx >> 4;
        wc[l] = idx & 15;
    }

    float acc[4][4][4];
#pragma unroll
    for (int mt = 0; mt < 4; mt++)
#pragma unroll
        for (int nb = 0; nb < 4; nb++)
#pragma unroll
            for (int j = 0; j < 4; j++) acc[mt][nb][j] = 0.f;

    float4 wv[4];
    // prologue: stage 0
#pragma unroll
    for (int l = 0; l < 8; l++) {
        int gr = row0 + xr[l];
        cp16g(smem_u32g(&Xs[xr[l] * XPAD + xc[l] * 4]),
              X + (size_t)gr * K + xc[l] * 4, (gr < M) ? 16 : 0);
    }
    cp_commitg();
#pragma unroll
    for (int l = 0; l < 4; l++)
        wv[l] = *(const float4*)(W + (size_t)wk[l] * HF + wc[l] * 4);
#pragma unroll
    for (int l = 0; l < 4; l++) {
        uint4 u = make_uint4(f2tf32(wv[l].x), f2tf32(wv[l].y), f2tf32(wv[l].z), f2tf32(wv[l].w));
        *(uint4*)&Ws[wk[l] * WPAD + wc[l] * 4] = u;
    }
    cp_waitg0();
    __syncthreads();

    for (int t = 0; t < nt; t++) {
        int cur = t & 1, nxt = 1 - cur;
        // issue next stage
        if (t + 1 < nt) {
            const float* Xn = X + (size_t)(t + 1) * BK;
            const float* Wn = W + (size_t)(t + 1) * BK * HF;
#pragma unroll
            for (int l = 0; l < 8; l++) {
                int gr = row0 + xr[l];
                cp16g(smem_u32g(&Xs[nxt * XSTAGE + xr[l] * XPAD + xc[l] * 4]),
                      Xn + (size_t)gr * K + xc[l] * 4, (gr < M) ? 16 : 0);
            }
            cp_commitg();
#pragma unroll
            for (int l = 0; l < 4; l++)
                wv[l] = *(const float4*)(Wn + (size_t)wk[l] * HF + wc[l] * 4);
        }

        // compute on stage cur
        const float*    Xc = Xs + cur * XSTAGE;
        const unsigned* Wt = Ws + cur * WSTAGE;
#pragma unroll
        for (int ks = 0; ks < 4; ks++) {
            int k0 = ks * 8;
            unsigned a[4][4];
#pragma unroll
            for (int mt = 0; mt < 4; mt++) {
                int r = rb + mt * 16 + lq;
                a[mt][0] = f2tf32(Xc[r * XPAD + k0 + lr]);
                a[mt][1] = f2tf32(Xc[(r + 8) * XPAD + k0 + lr]);
                a[mt][2] = f2tf32(Xc[r * XPAD + k0 + 4 + lr]);
                a[mt][3] = f2tf32(Xc[(r + 8) * XPAD + k0 + 4 + lr]);
            }
            unsigned b[4][2];
#pragma unroll
            for (int nb = 0; nb < 4; nb++) {
                int c = cb + nb * 8 + lq;
                b[nb][0] = Wt[(k0 + lr) * WPAD + c];
                b[nb][1] = Wt[(k0 + 4 + lr) * WPAD + c];
            }
#pragma unroll
            for (int mt = 0; mt < 4; mt++)
#pragma unroll
                for (int nb = 0; nb < 4; nb++)
                    asm volatile(
                        "mma.sync.aligned.m16n8k8.row.col.f32.tf32.tf32.f32 "
                        "{%0,%1,%2,%3}, {%4,%5,%6,%7}, {%8,%9}, {%0,%1,%2,%3};"
                        : "+f"(acc[mt][nb][0]), "+f"(acc[mt][nb][1]),
                          "+f"(acc[mt][nb][2]), "+f"(acc[mt][nb][3])
                        : "r"(a[mt][0]), "r"(a[mt][1]), "r"(a[mt][2]), "r"(a[mt][3]),
                          "r"(b[nb][0]), "r"(b[nb][1]));
        }

        if (t + 1 < nt) {
            // STS W(t+1) into nxt buffer (distinct from cur; safe pre-barrier)
#pragma unroll
            for (int l = 0; l < 4; l++) {
                uint4 u = make_uint4(f2tf32(wv[l].x), f2tf32(wv[l].y), f2tf32(wv[l].z), f2tf32(wv[l].w));
                *(uint4*)&Ws[nxt * WSTAGE + wk[l] * WPAD + wc[l] * 4] = u;
            }
            cp_waitg1();   // X stage t+1 may still be 1 pending? ensure stage t+1 done next iter
            __syncthreads();
            cp_waitg0();   // X(t+1) complete before anyone computes on it
            __syncthreads();
        }
    }

    // epilogue
#pragma unroll
    for (int mt = 0; mt < 4; mt++) {
#pragma unroll
        for (int nb = 0; nb < 4; nb++) {
            int r = row0 + rb + mt * 16 + lq;
            int c = cb + nb * 8 + 2 * lr;
            if (r < M)
                *(float2*)(Y + (size_t)r * HF + c) = make_float2(acc[mt][nb][0], acc[mt][nb][1]);
            if (r + 8 < M)
                *(float2*)(Y + (size_t)(r + 8) * HF + c) = make_float2(acc[mt][nb][2], acc[mt][nb][3]);
        }
    }
}

// ---------------- GCN aggregation (CSR, warp per dst node, 4-wide ILP) ----------------
__global__ void k_aggregate(const float* __restrict__ H, float* __restrict__ OUT,
                            const int* __restrict__ row, const int* __restrict__ srcs,
                            const float* __restrict__ dinv, const float* __restrict__ bias,
                            int N) {
    int warp = (blockIdx.x * blockDim.x + threadIdx.x) >> 5;
    int lane = threadIdx.x & 31;
    if (warp >= N) return;
    int dst = warp;
    float di = dinv[dst];
    const float2* Hp = (const float2*)H;
    float2 hs = Hp[(size_t)dst * 32 + lane];
    float2 acc = make_float2(hs.x * di, hs.y * di);
    int s = row[dst], e = row[dst + 1];
    int i = s;
    for (; i + 4 <= e; i += 4) {
        int i0 = srcs[i], i1 = srcs[i + 1], i2 = srcs[i + 2], i3 = srcs[i + 3];
        float d0 = dinv[i0], d1 = dinv[i1], d2 = dinv[i2], d3 = dinv[i3];
        float2 h0 = Hp[(size_t)i0 * 32 + lane];
        float2 h1 = Hp[(size_t)i1 * 32 + lane];
        float2 h2 = Hp[(size_t)i2 * 32 + lane];
        float2 h3 = Hp[(size_t)i3 * 32 + lane];
        acc.x += h0.x * d0; acc.y += h0.y * d0;
        acc.x += h1.x * d1; acc.y += h1.y * d1;
        acc.x += h2.x * d2; acc.y += h2.y * d2;
        acc.x += h3.x * d3; acc.y += h3.y * d3;
    }
    for (; i < e; i++) {
        int src = srcs[i];
        float ds = dinv[src];
        float2 h = Hp[(size_t)src * 32 + lane];
        acc.x += h.x * ds;
        acc.y += h.y * ds;
    }
    float2 b2 = ((const float2*)bias)[lane];
    float2 o = make_float2(acc.x * di + b2.x, acc.y * di + b2.y);
    ((float2*)OUT)[(size_t)dst * 32 + lane] = o;
}

// ---------------- fold Wproj/Wl1 into Wcomb, bcomb ----------------
__global__ void k_prepWc(const float* __restrict__ Wproj, const float* __restrict__ bproj,
                         const float* __restrict__ Wl1, const float* __restrict__ bl1,
                         float* __restrict__ Wc) {
    __shared__ float sWl1[128 * 64];
    for (int i = threadIdx.x; i < 128 * 64; i += blockDim.x) sWl1[i] = Wl1[i];
    __syncthreads();
    for (int o = threadIdx.x; o < 128 * 64; o += blockDim.x) {
        int i = o >> 6, j = o & 63;
        float s = 0.f;
        for (int k = 0; k < 128; k++) s += Wproj[i * 128 + k] * sWl1[k * 64 + j];
        Wc[o] = s;
    }
    for (int j = threadIdx.x; j < 64; j += blockDim.x) {
        float s = bl1[j];
        for (int k = 0; k < 128; k++) s += bproj[k] * sWl1[k * 64 + j];
        Wc[128 * 64 + j] = s;
    }
}

// ---------------- link predictor: out[e] = relu(Ap[ep]+As[es]+bc) . wl2 + bl2 ----------------
__global__ void k_link(const float* __restrict__ Ap, const float* __restrict__ As,
                       const int* __restrict__ ep, const int* __restrict__ es,
                       const float* __restrict__ bc, const float* __restrict__ wl2,
                       const float* __restrict__ bl2, float* __restrict__ out, int EL) {
    int warp = (blockIdx.x * blockDim.x + threadIdx.x) >> 5;
    int lane = threadIdx.x & 31;
    if (warp >= EL) return;
    int p = ep[warp];
    int s = es[warp];
    float2 a = ((const float2*)Ap)[(size_t)p * 32 + lane];
    float2 b = ((const float2*)As)[(size_t)s * 32 + lane];
    float2 c = ((const float2*)bc)[lane];
    float hx = fmaxf(a.x + b.x + c.x, 0.f);
    float hy = fmaxf(a.y + b.y + c.y, 0.f);
    float2 w = ((const float2*)wl2)[lane];
    float part = hx * w.x + hy * w.y;
#pragma unroll
    for (int off = 16; off; off >>= 1) part += __shfl_xor_sync(0xffffffffu, part, off);
    if (lane == 0) out[warp] = part + bl2[0];
}

// ---------------- host orchestration ----------------
static inline int cdiv(int a, int b) { return (a + b - 1) / b; }

extern "C" void kernel_launch(void* const* d_in, const int* in_sizes, int n_in,
                              void* d_out, int out_size) {
    const float* x_p  = (const float*)d_in[0];
    const float* x_s  = (const float*)d_in[1];
    const int*   ei_p = (const int*)d_in[2];
    const int*   ei_s = (const int*)d_in[3];
    const int*   ed_p = (const int*)d_in[4];
    const int*   ed_s = (const int*)d_in[5];
    const float* Wp1 = (const float*)d_in[6];
    const float* bp1 = (const float*)d_in[7];
    const float* Ws1 = (const float*)d_in[8];
    const float* bs1 = (const float*)d_in[9];
    const float* Wp2 = (const float*)d_in[10];
    const float* bp2 = (const float*)d_in[11];
    const float* Ws2 = (const float*)d_in[12];
    const float* bs2 = (const float*)d_in[13];
    const float* Wproj = (const float*)d_in[14];
    const float* bproj = (const float*)d_in[15];
    const float* Wl1 = (const float*)d_in[16];
    const float* bl1 = (const float*)d_in[17];
    const float* Wl2 = (const float*)d_in[18];
    const float* bl2 = (const float*)d_in[19];
    float* out = (float*)d_out;

    float *bufP0, *bufP1, *bufS0, *bufS1, *dinvP, *dinvS, *Wc;
    int *rowP, *rowS, *curP, *curS, *srcP, *srcS, *bsum;
    cudaGetSymbolAddress((void**)&bufP0, g_bufP0);
    cudaGetSymbolAddress((void**)&bufP1, g_bufP1);
    cudaGetSymbolAddress((void**)&bufS0, g_bufS0);
    cudaGetSymbolAddress((void**)&bufS1, g_bufS1);
    cudaGetSymbolAddress((void**)&dinvP, g_dinvP);
    cudaGetSymbolAddress((void**)&dinvS, g_dinvS);
    cudaGetSymbolAddress((void**)&rowP,  g_rowP);
    cudaGetSymbolAddress((void**)&rowS,  g_rowS);
    cudaGetSymbolAddress((void**)&curP,  g_curP);
    cudaGetSymbolAddress((void**)&curS,  g_curS);
    cudaGetSymbolAddress((void**)&srcP,  g_srcP);
    cudaGetSymbolAddress((void**)&srcS,  g_srcS);
    cudaGetSymbolAddress((void**)&Wc,    g_Wc);
    cudaGetSymbolAddress((void**)&bsum,  g_bsum);

    cudaFuncSetAttribute(k_gemm, cudaFuncAttributeMaxDynamicSharedMemorySize, GEMM_SMEM);

    const int EP = in_sizes[2] / 2;
    const int ES = in_sizes[3] / 2;
    const int EL = in_sizes[4];
    const int nbP = cdiv(NP, 1024), nbS = cdiv(NS, 1024);

    // ---- CSR build prefix; big GEMM placed as 4th launch (lands in ncu window) ----
    k_countB<<<cdiv(EP + ES, 256), 256>>>(ei_p, EP, ei_s, ES, curP, curS);
    k_scan1B<<<nbP + nbS, 1024>>>(curP, curS, rowP, rowS, bsum, nbP);
    k_scan2B<<<1, 1024>>>(bsum, nbP, nbS);
    k_gemm<<<cdiv(NP, BM), 128, GEMM_SMEM>>>(x_p, Wp1, bufP0, NP, PD);  // <- profiled
    k_scan3B<<<cdiv(NP + NS, 256), 256>>>(rowP, rowS, curP, curS, bsum, nbP, EP, ES, dinvP, dinvS);
    k_fillB<<<cdiv(EP + ES, 256), 256>>>(ei_p, EP, ei_s, ES, curP, curS, srcP, srcS);
    k_gemm<<<cdiv(NS, BM), 128, GEMM_SMEM>>>(x_s, Ws1, bufS0, NS, SD);
    k_prepWc<<<1, 256>>>(Wproj, bproj, Wl1, bl1, Wc);

    // ---- protein GCN ----
    k_aggregate<<<cdiv(NP * 32, 256), 256>>>(bufP0, bufP1, rowP, srcP, dinvP, bp1, NP);
    k_gemm<<<cdiv(NP, BM), 128, GEMM_SMEM>>>(bufP1, Wp2, bufP0, NP, HF);
    k_aggregate<<<cdiv(NP * 32, 256), 256>>>(bufP0, bufP1, rowP, srcP, dinvP, bp2, NP);

    // ---- substrate GCN ----
    k_aggregate<<<cdiv(NS * 32, 256), 256>>>(bufS0, bufS1, rowS, srcS, dinvS, bs1, NS);
    k_gemm<<<cdiv(NS, BM), 128, GEMM_SMEM>>>(bufS1, Ws2, bufS0, NS, HF);
    k_aggregate<<<cdiv(NS * 32, 256), 256>>>(bufS0, bufS1, rowS, srcS, dinvS, bs2, NS);

    // ---- per-node link features: Ap = z_p @ Wc_top, As = z_s @ Wc_bot ----
    k_gemm<<<cdiv(NP, BM), 128, GEMM_SMEM>>>(bufP1, Wc, bufP0, NP, HF);
    k_gemm<<<cdiv(NS, BM), 128, GEMM_SMEM>>>(bufS1, Wc + 64 * 64, bufS0, NS, HF);

    // ---- link prediction ----
    {
        long long threads = (long long)EL * 32;
        int blocks = (int)((threads + 255) / 256);
        k_link<<<blocks, 256>>>(bufP0, bufS0, ed_p, ed_s, Wc + 128 * 64, Wl2, bl2, out, EL);
    }

    // ---- restore cursor arrays for next replay ----
    k_reset<<<cdiv(NP, 256), 256>>>(curP, curS);
}